// round 11
// baseline (speedup 1.0000x reference)
#include <cuda_runtime.h>
#include <cuda_fp16.h>
#include <cstdint>

#define NTOK 8192
#define DIM  2048
#define NEXP 8
#define TOPK 2

#define BM 128
#define BN 128
#define BK 64                          // halves per k-iter
#define STAGES 3
#define KITERS (DIM / BK)              // 32

#define GRID_ROWTILES 136

#define STAGE_BYTES (BM * BK * 2)      // 16384
#define SMEM_TOTAL  (2 * STAGES * STAGE_BYTES)  // 98304

#define GATE_BLOCKS 1024               // 8 warps/block, 1 token/warp
#define CONV_BLOCKS 2048               // W-convert + out-zero slices
#define PREP_BLOCKS (GATE_BLOCKS + CONV_BLOCKS)

// ---------------- device globals ----------------
__device__ int    g_count[NEXP];
__device__ int    g_tok[NEXP * NTOK];
__device__ float  g_wt [NEXP * NTOK];
__device__ __half g_xh[(size_t)NEXP * NTOK * DIM];   // per-expert padded fp16 A
__device__ __half g_wh[(size_t)NEXP * DIM * DIM];    // fp16 W

// ---------------- helpers ----------------
__device__ __forceinline__ uint32_t smem_u32(const void* p) {
    uint32_t a;
    asm("{ .reg .u64 t; cvta.to.shared.u64 t, %1; cvt.u32.u64 %0, t; }" : "=r"(a) : "l"(p));
    return a;
}
#define CP16(dst, src) \
    asm volatile("cp.async.cg.shared.global [%0], [%1], 16;" :: "r"(dst), "l"(src) : "memory")
#define CP_COMMIT() asm volatile("cp.async.commit_group;" ::: "memory")
#define CP_WAIT1()  asm volatile("cp.async.wait_group 1;" ::: "memory")
#define CP_WAIT0()  asm volatile("cp.async.wait_group 0;" ::: "memory")

#define LDSM4(r0, r1, r2, r3, addr) \
    asm volatile("ldmatrix.sync.aligned.m8n8.x4.shared.b16 {%0,%1,%2,%3}, [%4];" \
        : "=r"(r0), "=r"(r1), "=r"(r2), "=r"(r3) : "r"(addr))

__device__ __forceinline__ void mma_f16(float* d, const uint32_t* a, const uint32_t* b) {
    asm volatile(
        "mma.sync.aligned.m16n8k16.row.col.f32.f16.f16.f32 "
        "{%0,%1,%2,%3}, {%4,%5,%6,%7}, {%8,%9}, {%0,%1,%2,%3};"
        : "+f"(d[0]), "+f"(d[1]), "+f"(d[2]), "+f"(d[3])
        : "r"(a[0]), "r"(a[1]), "r"(a[2]), "r"(a[3]), "r"(b[0]), "r"(b[1]));
}

// ---------------- kernel 0: init counters ----------------
__global__ void init_kernel() {
    if (threadIdx.x < NEXP) g_count[threadIdx.x] = 0;
}

// ---------------- kernel 1: fused prep ----------------
__global__ void __launch_bounds__(256)
prep_kernel(const float* __restrict__ x,
            const float4* __restrict__ W,
            const float* __restrict__ Wg,
            const float* __restrict__ bg,
            float4* __restrict__ out) {
    int bid = blockIdx.x;
    int tid = threadIdx.x;

    if (bid >= GATE_BLOCKS) {
        int cid = bid - GATE_BLOCKS;
        {
            __half2* dst = (__half2*)g_wh;
            size_t base = (size_t)cid * 4096 + tid;
#pragma unroll 4
            for (int i = 0; i < 16; i++) {
                size_t idx = base + (size_t)i * 256;
                float4 v = W[idx];
                dst[2 * idx]     = __floats2half2_rn(v.x, v.y);
                dst[2 * idx + 1] = __floats2half2_rn(v.z, v.w);
            }
        }
        {
            float4 z = make_float4(0.f, 0.f, 0.f, 0.f);
            size_t base = (size_t)cid * 2048 + tid;
#pragma unroll
            for (int i = 0; i < 8; i++)
                out[base + (size_t)i * 256] = z;
        }
        return;
    }

    int wid  = tid >> 5;
    int lane = tid & 31;
    int tok  = bid * 8 + wid;

    const float* xr = x + (size_t)tok * DIM;
    float acc[NEXP];
#pragma unroll
    for (int e = 0; e < NEXP; e++) acc[e] = 0.f;
    for (int i = lane; i < DIM; i += 32) {
        float xv = xr[i];
#pragma unroll
        for (int e = 0; e < NEXP; e++)
            acc[e] = fmaf(xv, Wg[e * DIM + i], acc[e]);
    }
#pragma unroll
    for (int off = 16; off; off >>= 1)
#pragma unroll
        for (int e = 0; e < NEXP; e++)
            acc[e] += __shfl_xor_sync(0xffffffffu, acc[e], off);

    int i0 = 0, i1 = 0, p0 = 0, p1 = 0;
    if (lane == 0) {
        float m = -3.4e38f;
#pragma unroll
        for (int e = 0; e < NEXP; e++) { acc[e] += bg[e]; m = fmaxf(m, acc[e]); }
        float p[NEXP], s = 0.f;
#pragma unroll
        for (int e = 0; e < NEXP; e++) { p[e] = expf(acc[e] - m); s += p[e]; }
        i0 = 0;
#pragma unroll
        for (int e = 1; e < NEXP; e++) if (p[e] > p[i0]) i0 = e;
        i1 = (i0 == 0) ? 1 : 0;
#pragma unroll
        for (int e = 0; e < NEXP; e++)
            if (e != i0 && p[e] > p[i1]) i1 = e;

        float inv = 1.f / s;
        p0 = atomicAdd(&g_count[i0], 1);
        p1 = atomicAdd(&g_count[i1], 1);
        g_tok[i0 * NTOK + p0] = tok;  g_wt[i0 * NTOK + p0] = p[i0] * inv;
        g_tok[i1 * NTOK + p1] = tok;  g_wt[i1 * NTOK + p1] = p[i1] * inv;
    }
    i0 = __shfl_sync(0xffffffffu, i0, 0);
    i1 = __shfl_sync(0xffffffffu, i1, 0);
    p0 = __shfl_sync(0xffffffffu, p0, 0);
    p1 = __shfl_sync(0xffffffffu, p1, 0);

    const float4* src = (const float4*)xr;
    __half2* d0 = (__half2*)(g_xh + ((size_t)i0 * NTOK + p0) * DIM);
    __half2* d1 = (__half2*)(g_xh + ((size_t)i1 * NTOK + p1) * DIM);
    for (int i = lane; i < DIM / 4; i += 32) {
        float4 v = src[i];
        __half2 h0 = __floats2half2_rn(v.x, v.y);
        __half2 h1 = __floats2half2_rn(v.z, v.w);
        d0[2 * i] = h0; d0[2 * i + 1] = h1;
        d1[2 * i] = h0; d1[2 * i + 1] = h1;
    }
}

// ---------------- kernel 2: FP16 mma.sync grouped GEMM ----------------
// 256 thr, warps 4(M)x2(N), warp tile 32x64.  PHASE-ROTATED k16 order:
// warp_m group w processes k16 blocks in order (j + w) & 3, so at any
// instant the 4 groups are in different LDSM/HMMA phases -> crossbar
// stream uniform, tensor pipe stays fed.  A frags double-buffered,
// B pairs JIT-rotated, 3-stage cp.async, one barrier per k-tile.
__global__ void __launch_bounds__(256, 2)
moe_mma_gemm(const float* __restrict__ bias, float* __restrict__ out) {
    int bx = blockIdx.x;

    // derive (expert, row-tile) from counts
    int e = -1, r0 = 0, nt = 0;
#pragma unroll
    for (int i = 0; i < NEXP; i++) {
        int t = (g_count[i] + BM - 1) / BM;
        if (e < 0 && bx < nt + t) { e = i; r0 = (bx - nt) * BM; }
        nt += t;
    }
    if (e < 0) return;
    int cnt = g_count[e];
    int n0  = blockIdx.y * BN;

    extern __shared__ char smem[];
    uint32_t sbase = smem_u32(smem);

    int tid    = threadIdx.x;
    int lane   = tid & 31;
    int wid    = tid >> 5;
    int warp_m = wid & 3;
    int warp_n = wid >> 2;
    int fr     = lane >> 2;
    int fc     = lane & 3;

    int lrow = tid >> 1;
    int cgrp = (tid & 1) * 4;
    const __half* gA = g_xh + ((size_t)e * NTOK + r0 + lrow) * DIM + cgrp * 8;
    const __half* gB = g_wh + ((size_t)e * DIM + n0 + lrow) * DIM + cgrp * 8;
    uint32_t rowOff = lrow * 128;
    int      rSw    = lrow & 7;

    int mi  = lane >> 3;
    int r8  = lane & 7;
    int aCh = mi >> 1;
    uint32_t aBase[2];
    int      aSw[2];
#pragma unroll
    for (int tm = 0; tm < 2; tm++) {
        int r = warp_m * 32 + tm * 16 + (mi & 1) * 8 + r8;
        aBase[tm] = r * 128;
        aSw[tm]   = r & 7;
    }
    int bCh = mi & 1;
    uint32_t bBase[4];
    int      bSw[4];
#pragma unroll
    for (int p = 0; p < 4; p++) {
        int r = warp_n * 64 + (2 * p + (mi >> 1)) * 8 + r8;
        bBase[p] = r * 128;
        bSw[p]   = r & 7;
    }

    float acc[2][8][4];
#pragma unroll
    for (int i = 0; i < 2; i++)
#pragma unroll
        for (int j = 0; j < 8; j++)
#pragma unroll
            for (int k = 0; k < 4; k++) acc[i][j][k] = 0.f;

    auto load_stage = [&](int s, int kt) {
        uint32_t da = sbase + s * STAGE_BYTES + rowOff;
        uint32_t db = sbase + (STAGES + s) * STAGE_BYTES + rowOff;
        const __half* pa = gA + kt * BK;
        const __half* pb = gB + kt * BK;
#pragma unroll
        for (int c = 0; c < 4; c++) {
            uint32_t pc = (uint32_t)((cgrp + c) ^ rSw) << 4;
            CP16(da + pc, pa + c * 8);
            CP16(db + pc, pb + c * 8);
        }
        CP_COMMIT();
    };

    // fragment buffers: A double (per k16 step), B 2-slot pair rotation
    uint32_t a[2][2][4], b[2][4];

    auto load_a = [&](int buf, int kk, uint32_t As) {
#pragma unroll
        for (int tm = 0; tm < 2; tm++) {
            uint32_t addr = As + aBase[tm] +
                            ((uint32_t)((kk * 2 + aCh) ^ aSw[tm]) << 4);
            LDSM4(a[buf][tm][0], a[buf][tm][1], a[buf][tm][2], a[buf][tm][3], addr);
        }
    };
    auto load_b = [&](int buf, int kk, int p, uint32_t Bs) {
        uint32_t addr = Bs + bBase[p] +
                        ((uint32_t)((kk * 2 + bCh) ^ bSw[p]) << 4);
        LDSM4(b[buf][0], b[buf][1], b[buf][2], b[buf][3], addr);
    };

#pragma unroll
    for (int s = 0; s < STAGES - 1; s++) load_stage(s, s);

#pragma unroll 1
    for (int kt = 0; kt < KITERS; kt++) {
        if (kt < KITERS - 1) { CP_WAIT1(); } else { CP_WAIT0(); }
        __syncthreads();   // prior-iter reads done; stage kt resident

        uint32_t As = sbase + (kt % STAGES) * STAGE_BYTES;
        uint32_t Bs = sbase + (STAGES + (kt % STAGES)) * STAGE_BYTES;

        // phase-rotated first fragments: this warp starts at kk = warp_m & 3
        int kk0 = warp_m & 3;
        load_a(0, kk0, As);
        load_b(0, kk0, 0, Bs);

        int kp = kt + STAGES - 1;
        if (kp < KITERS) load_stage(kp % STAGES, kp);

#pragma unroll
        for (int j = 0; j < BK / 16; j++) {
            int kk  = (j + warp_m) & 3;          // rotated k16 order
            int kkn = (j + 1 + warp_m) & 3;
            int cur = j & 1;
            if (j < BK / 16 - 1) load_a(cur ^ 1, kkn, As);
#pragma unroll
            for (int p = 0; p < 4; p++) {
                int pb = p & 1;
                if (p < 3)                load_b(pb ^ 1, kk,  p + 1, Bs);
                else if (j < BK / 16 - 1) load_b(pb ^ 1, kkn, 0,     Bs);
#pragma unroll
                for (int tm = 0; tm < 2; tm++) {
                    mma_f16(acc[tm][2 * p],     a[cur][tm], &b[pb][0]);
                    mma_f16(acc[tm][2 * p + 1], a[cur][tm], &b[pb][2]);
                }
            }
        }
    }

    // epilogue: bias + relu + gate weight -> atomicAdd into out
    int c2 = 2 * fc;
    float2 bv[8];
#pragma unroll
    for (int tn = 0; tn < 8; tn++) {
        const float* bp = bias + (size_t)e * DIM + n0 + warp_n * 64 + tn * 8 + c2;
        bv[tn] = make_float2(__ldg(bp), __ldg(bp + 1));
    }
#pragma unroll
    for (int tm = 0; tm < 2; tm++) {
#pragma unroll
        for (int half = 0; half < 2; half++) {
            int row = warp_m * 32 + tm * 16 + half * 8 + fr;
            int idx = r0 + row;
            if (idx >= cnt) continue;
            int   tok = g_tok[e * NTOK + idx];
            float wgt = g_wt [e * NTOK + idx];
            float* orow = out + (size_t)tok * DIM + n0 + warp_n * 64;
#pragma unroll
            for (int tn = 0; tn < 8; tn++) {
                float v0 = fmaxf(acc[tm][tn][half * 2 + 0] + bv[tn].x, 0.f) * wgt;
                float v1 = fmaxf(acc[tm][tn][half * 2 + 1] + bv[tn].y, 0.f) * wgt;
                atomicAdd(orow + tn * 8 + c2,     v0);
                atomicAdd(orow + tn * 8 + c2 + 1, v1);
            }
        }
    }
}

// ---------------- launch ----------------
extern "C" void kernel_launch(void* const* d_in, const int* in_sizes, int n_in,
                              void* d_out, int out_size) {
    const float* x  = (const float*)d_in[0];
    const float* W  = (const float*)d_in[1];
    const float* b  = (const float*)d_in[2];
    const float* Wg = (const float*)d_in[3];
    const float* bg = (const float*)d_in[4];
    float* out = (float*)d_out;
    (void)in_sizes; (void)n_in; (void)out_size;

    cudaFuncSetAttribute(moe_mma_gemm, cudaFuncAttributeMaxDynamicSharedMemorySize, SMEM_TOTAL);

    init_kernel<<<1, 32>>>();
    prep_kernel<<<PREP_BLOCKS, 256>>>(x, (const float4*)W, Wg, bg, (float4*)out);
    moe_mma_gemm<<<dim3(GRID_ROWTILES, DIM / BN), 256, SMEM_TOTAL>>>(b, out);
}